// round 10
// baseline (speedup 1.0000x reference)
#include <cuda_runtime.h>
#include <cuda_bf16.h>
#include <math.h>

#define VOCAB 50000
#define D 256
#define Bn 128
#define Sn 64
#define Ln 32
#define Kn 32

// Scratch (device globals: allocation-free rule)
__device__ float  g_enc [Bn * Sn * D];          // enc_sents   (B,S,D)
__device__ float  g_encW[Bn * Sn * D];          // enc_sents@W (B,S,D)
__device__ float  g_keysV[Bn * Kn * D];         // keys@V      (B,K,D)
__device__ float  g_eK  [Bn * Sn * Kn];         // enc·keys    (B,S,K)
__device__ float2 g_Upk [(D / 2) * D];          // U packed: [p][c] = (U[2p][c], U[2p+1][c])

#define FMA_F32X2(d_, a_, b_, c_) \
    asm("fma.rn.f32x2 %0, %1, %2, %3;" : "=l"(d_) : "l"(a_), "l"(b_), "l"(c_))

// ---------------------------------------------------------------------------
// Fused: enc_sents[b,s,d] = sum_l emb[prgrph[b,s,l], d]
//        eK[b,s,k]        = sum_d enc[b,s,d] * keys[b,k,d]
// ---------------------------------------------------------------------------
__global__ void gather_eK_kernel(const int* __restrict__ prgrph,
                                 const float* __restrict__ emb,
                                 const float* __restrict__ keys) {
    __shared__ int   sidx[Ln];
    __shared__ float e_sh[D];
    int bs = blockIdx.x;
    int b  = bs / Sn;
    int t  = threadIdx.x;
    int w  = t >> 5, lane = t & 31;
    if (t < Ln) sidx[t] = prgrph[(size_t)bs * Ln + t];
    __syncthreads();
    float acc = 0.f;
#pragma unroll
    for (int l = 0; l < Ln; ++l) acc += __ldg(emb + (size_t)sidx[l] * D + t);
    g_enc[(size_t)bs * D + t] = acc;
    e_sh[t] = acc;
    __syncthreads();
#pragma unroll
    for (int r = 0; r < 4; ++r) {
        int k = w * 4 + r;
        const float* kr = keys + ((size_t)b * Kn + k) * D;
        float p = 0.f;
#pragma unroll
        for (int j = 0; j < 8; ++j) {
            int c = lane + 32 * j;
            p = fmaf(e_sh[c], __ldg(kr + c), p);
        }
#pragma unroll
        for (int o = 16; o > 0; o >>= 1) p += __shfl_xor_sync(0xffffffffu, p, o);
        if (lane == 0) g_eK[(size_t)bs * Kn + k] = p;
    }
}

// ---------------------------------------------------------------------------
__global__ void packU_kernel(const float* __restrict__ U) {
    int p = blockIdx.x;
    int c = threadIdx.x;
    g_Upk[p * D + c] = make_float2(U[(2 * p) * D + c], U[(2 * p + 1) * D + c]);
}

// ---------------------------------------------------------------------------
// 16-row GEMM tile: C[16,D] = A[16,D] @ Bm[D,D]
// ---------------------------------------------------------------------------
__device__ __forceinline__ void gemm16_body(const float* __restrict__ Ab,
                                            const float* __restrict__ Bm,
                                            float* __restrict__ Cb) {
    __shared__ float a_sh[16 * D];
    int t = threadIdx.x;
    for (int i = t; i < 16 * D; i += 256) a_sh[i] = Ab[i];
    __syncthreads();

    float acc[16];
#pragma unroll
    for (int k = 0; k < 16; ++k) acc[k] = 0.f;

    for (int d0 = 0; d0 < D; d0 += 8) {
        float u[8];
#pragma unroll
        for (int i = 0; i < 8; ++i) u[i] = __ldg(Bm + (size_t)(d0 + i) * D + t);
#pragma unroll
        for (int k = 0; k < 16; ++k) {
            float4 h1 = *(const float4*)&a_sh[k * D + d0];
            float4 h2 = *(const float4*)&a_sh[k * D + d0 + 4];
            acc[k] = fmaf(h1.x, u[0], acc[k]); acc[k] = fmaf(h1.y, u[1], acc[k]);
            acc[k] = fmaf(h1.z, u[2], acc[k]); acc[k] = fmaf(h1.w, u[3], acc[k]);
            acc[k] = fmaf(h2.x, u[4], acc[k]); acc[k] = fmaf(h2.y, u[5], acc[k]);
            acc[k] = fmaf(h2.z, u[6], acc[k]); acc[k] = fmaf(h2.w, u[7], acc[k]);
        }
    }
#pragma unroll
    for (int k = 0; k < 16; ++k) Cb[k * D + t] = acc[k];
}

// encW tiles (0..511) + keysV tiles (512..767)
__global__ void gemm_pre_kernel(const float* __restrict__ keys,
                                const float* __restrict__ V,
                                const float* __restrict__ W) {
    int blk = blockIdx.x;
    if (blk < 512) {
        size_t off = (size_t)blk * 16 * D;
        gemm16_body(g_enc + off, W, g_encW + off);
    } else {
        size_t off = (size_t)(blk - 512) * 16 * D;
        gemm16_body(keys + off, V, g_keysV + off);
    }
}

// ---------------------------------------------------------------------------
// The scan. 512 CTAs = (batch, 8-row quarter); rows fully independent.
// 256 threads/CTA, 3 CTAs/SM. Thread t: adjacent cols c0=2*(t&127), c1=c0+1;
// group g=t>>7 -> local rows g*4 .. g*4+3.
// Gate dot for the NEXT active step is fused into the epilogue reduction
// (h_new is in registers), so each step is: GEMM -> S1 -> epilogue -> S2 ->
// 8-thread combine (rs + gate). h kept UNNORMALIZED in smem.
// ---------------------------------------------------------------------------
#define KQ 8   // rows per CTA

__global__ void __launch_bounds__(256, 3)
scan_kernel(const int* __restrict__ pmask,
            float* __restrict__ out) {
    __shared__ float h[KQ * D];          // 8 KB, unnormalized local rows
    __shared__ float gate_sh[KQ];
    __shared__ float rs_sh[KQ];
    __shared__ float np_sh[KQ * 4];
    __shared__ float gd_sh[KQ * 4];
    __shared__ int   nextact[Sn];
    __shared__ int   s0_sh;

    const int b    = blockIdx.x >> 2;
    const int qtr  = blockIdx.x & 3;
    const int kgbl = qtr * KQ;           // global row base
    const int t    = threadIdx.x;
    const int cp   = t & 127;
    const int c0   = cp * 2;
    const int g    = t >> 7;             // 0..1
    const int kb   = g * 4;              // local rows kb..kb+3
    const int w    = t >> 5;             // 0..7
    const int wj   = w & 3;
    const int lane = t & 31;

    const size_t encRow = (size_t)b * Sn;

    // next-active table (thread 0, once)
    if (t == 0) {
        int nxt = -1;
        for (int s = Sn - 1; s >= 0; --s) {
            nextact[s] = nxt;
            if (pmask[(encRow + s) * Ln] != 0) nxt = s;
        }
        s0_sh = nxt;
    }

    // persistent registers: this thread's h values + loop-invariant keysV
    float hrA[4], hrB[4], kvA[4], kvB[4];
#pragma unroll
    for (int r = 0; r < 4; ++r) {
        hrA[r] = 0.f; hrB[r] = 0.f;
        float2 kv = __ldg((const float2*)
            (g_keysV + ((size_t)b * Kn + kgbl + kb + r) * D + c0));
        kvA[r] = kv.x; kvB[r] = kv.y;
    }
    for (int i = t; i < KQ * D; i += 256) h[i] = 0.f;
    if (t < KQ) rs_sh[t] = 1.f;
    __syncthreads();

    int s = s0_sh;
    // first gate: h = 0 -> gate = sigmoid(eK)
    if (s >= 0 && t < KQ) {
        float ek = __ldg(g_eK + (encRow + s) * Kn + kgbl + t);
        gate_sh[t] = 1.f / (1.f + expf(-ek));
    }
    __syncthreads();

    const ulonglong2* Upk2 = (const ulonglong2*)g_Upk;   // [p][cp] 16B units

    while (s >= 0) {
        const int snext = nextact[s];

        // ---- GEMM: acc = h_raw @ U, 4 local rows x 2 adjacent cols ----
        unsigned long long accA[4], accB[4];
#pragma unroll
        for (int r = 0; r < 4; ++r) { accA[r] = 0ull; accB[r] = 0ull; }

#pragma unroll 4
        for (int p4 = 0; p4 < D / 2; p4 += 4) {
            ulonglong2 u0 = __ldg(Upk2 + (size_t)(p4 + 0) * 128 + cp);
            ulonglong2 u1 = __ldg(Upk2 + (size_t)(p4 + 1) * 128 + cp);
            ulonglong2 u2 = __ldg(Upk2 + (size_t)(p4 + 2) * 128 + cp);
            ulonglong2 u3 = __ldg(Upk2 + (size_t)(p4 + 3) * 128 + cp);
#pragma unroll
            for (int r = 0; r < 4; ++r) {
                const ulonglong2* hp =
                    (const ulonglong2*)&h[(kb + r) * D + p4 * 2];
                ulonglong2 h01 = hp[0];
                ulonglong2 h23 = hp[1];
                FMA_F32X2(accA[r], h01.x, u0.x, accA[r]);
                FMA_F32X2(accB[r], h01.x, u0.y, accB[r]);
                FMA_F32X2(accA[r], h01.y, u1.x, accA[r]);
                FMA_F32X2(accB[r], h01.y, u1.y, accB[r]);
                FMA_F32X2(accA[r], h23.x, u2.x, accA[r]);
                FMA_F32X2(accB[r], h23.x, u2.y, accB[r]);
                FMA_F32X2(accA[r], h23.y, u3.x, accA[r]);
                FMA_F32X2(accB[r], h23.y, u3.y, accB[r]);
            }
        }
        __syncthreads();   // S1: old-h reads done; gate_sh/rs_sh stable

        // ---- epilogue: new h + fused norm/gate-dot partials ----
        const float2 ew = __ldg((const float2*)(g_encW + (encRow + s) * D + c0));
        float2 en = make_float2(0.f, 0.f);
        if (snext >= 0)
            en = __ldg((const float2*)(g_enc + (encRow + snext) * D + c0));

        float np[4], gd[4];
#pragma unroll
        for (int r = 0; r < 4; ++r) {
            int   k  = kb + r;
            float rs = rs_sh[k];
            float gt = gate_sh[k];
            float2 aA = *(float2*)&accA[r];
            float2 aB = *(float2*)&accB[r];
            float htA = fmaxf(fmaf(rs, aA.x + aA.y, kvA[r] + ew.x), 0.f);
            float htB = fmaxf(fmaf(rs, aB.x + aB.y, kvB[r] + ew.y), 0.f);
            hrA[r] = fmaf(gt, htA, rs * hrA[r]);
            hrB[r] = fmaf(gt, htB, rs * hrB[r]);
            *(float2*)&h[k * D + c0] = make_float2(hrA[r], hrB[r]);
            np[r] = fmaf(hrA[r], hrA[r], hrB[r] * hrB[r]);
            gd[r] = fmaf(en.x, hrA[r], en.y * hrB[r]);
        }
#pragma unroll
        for (int o = 16; o > 0; o >>= 1) {
#pragma unroll
            for (int r = 0; r < 4; ++r) {
                np[r] += __shfl_xor_sync(0xffffffffu, np[r], o);
                gd[r] += __shfl_xor_sync(0xffffffffu, gd[r], o);
            }
        }
        if (lane == 0) {
#pragma unroll
            for (int r = 0; r < 4; ++r) {
                np_sh[(kb + r) * 4 + wj] = np[r];
                gd_sh[(kb + r) * 4 + wj] = gd[r];
            }
        }
        __syncthreads();   // S2: partials ready, new h visible

        // ---- combine: rs + next gate (8 threads) ----
        if (t < KQ) {
            float ssum = np_sh[t * 4 + 0] + np_sh[t * 4 + 1] +
                         np_sh[t * 4 + 2] + np_sh[t * 4 + 3];
            float rs = rsqrtf(fmaxf(ssum, 1e-12f));
            rs_sh[t] = rs;
            if (snext >= 0) {
                float gsum = gd_sh[t * 4 + 0] + gd_sh[t * 4 + 1] +
                             gd_sh[t * 4 + 2] + gd_sh[t * 4 + 3];
                float ek = __ldg(g_eK + (encRow + snext) * Kn + kgbl + t);
                gate_sh[t] = 1.f / (1.f + expf(-(fmaf(rs, gsum, ek))));
            }
        }
        s = snext;
        // rs_sh/gate_sh consumed next step after S1 (ordered); final
        // consumption after the loop is ordered by the barrier below.
    }

    __syncthreads();   // final rs_sh visibility
#pragma unroll
    for (int r = 0; r < 4; ++r) {
        int k = kb + r;
        *(float2*)&out[((size_t)b * Kn + kgbl + k) * D + c0] =
            make_float2(hrA[r] * rs_sh[k], hrB[r] * rs_sh[k]);
    }
}

// ---------------------------------------------------------------------------
extern "C" void kernel_launch(void* const* d_in, const int* in_sizes, int n_in,
                              void* d_out, int out_size) {
    const int*   prgrph = (const int*)d_in[0];
    const int*   pmask  = (const int*)d_in[1];
    const float* keys   = (const float*)d_in[2];
    const float* emb    = (const float*)d_in[3];
    const float* U      = (const float*)d_in[4];
    const float* V      = (const float*)d_in[5];
    const float* W      = (const float*)d_in[6];
    float*       out    = (float*)d_out;

    gather_eK_kernel<<<Bn * Sn, 256>>>(prgrph, emb, keys);
    packU_kernel<<<D / 2, 256>>>(U);
    gemm_pre_kernel<<<768, 256>>>(keys, V, W);
    scan_kernel<<<Bn * 4, 256>>>(pmask, out);
}

// round 11
// speedup vs baseline: 1.2658x; 1.2658x over previous
#include <cuda_runtime.h>
#include <cuda_bf16.h>
#include <math.h>

#define VOCAB 50000
#define D 256
#define Bn 128
#define Sn 64
#define Ln 32
#define Kn 32

// Scratch (device globals: allocation-free rule)
__device__ float  g_enc [Bn * Sn * D];          // enc_sents   (B,S,D)
__device__ float  g_encW[Bn * Sn * D];          // enc_sents@W (B,S,D)
__device__ float  g_keysV[Bn * Kn * D];         // keys@V      (B,K,D)
__device__ float  g_eK  [Bn * Sn * Kn];         // enc·keys    (B,S,K)
__device__ float2 g_Upk [(D / 2) * D];          // U packed: [p][c] = (U[2p][c], U[2p+1][c])

#define FMA_F32X2(d_, a_, b_, c_) \
    asm("fma.rn.f32x2 %0, %1, %2, %3;" : "=l"(d_) : "l"(a_), "l"(b_), "l"(c_))

// ---------------------------------------------------------------------------
// Fused: enc_sents[b,s,d] = sum_l emb[prgrph[b,s,l], d]
//        eK[b,s,k]        = sum_d enc[b,s,d] * keys[b,k,d]
// ---------------------------------------------------------------------------
__global__ void gather_eK_kernel(const int* __restrict__ prgrph,
                                 const float* __restrict__ emb,
                                 const float* __restrict__ keys) {
    __shared__ int   sidx[Ln];
    __shared__ float e_sh[D];
    int bs = blockIdx.x;
    int b  = bs / Sn;
    int t  = threadIdx.x;
    int w  = t >> 5, lane = t & 31;
    if (t < Ln) sidx[t] = prgrph[(size_t)bs * Ln + t];
    __syncthreads();
    float acc = 0.f;
#pragma unroll
    for (int l = 0; l < Ln; ++l) acc += __ldg(emb + (size_t)sidx[l] * D + t);
    g_enc[(size_t)bs * D + t] = acc;
    e_sh[t] = acc;
    __syncthreads();
#pragma unroll
    for (int r = 0; r < 4; ++r) {
        int k = w * 4 + r;
        const float* kr = keys + ((size_t)b * Kn + k) * D;
        float p = 0.f;
#pragma unroll
        for (int j = 0; j < 8; ++j) {
            int c = lane + 32 * j;
            p = fmaf(e_sh[c], __ldg(kr + c), p);
        }
#pragma unroll
        for (int o = 16; o > 0; o >>= 1) p += __shfl_xor_sync(0xffffffffu, p, o);
        if (lane == 0) g_eK[(size_t)bs * Kn + k] = p;
    }
}

// ---------------------------------------------------------------------------
__global__ void packU_kernel(const float* __restrict__ U) {
    int p = blockIdx.x;
    int c = threadIdx.x;
    g_Upk[p * D + c] = make_float2(U[(2 * p) * D + c], U[(2 * p + 1) * D + c]);
}

// ---------------------------------------------------------------------------
// 16-row GEMM tile: C[16,D] = A[16,D] @ Bm[D,D]
// ---------------------------------------------------------------------------
__device__ __forceinline__ void gemm16_body(const float* __restrict__ Ab,
                                            const float* __restrict__ Bm,
                                            float* __restrict__ Cb) {
    __shared__ float a_sh[16 * D];
    int t = threadIdx.x;
    for (int i = t; i < 16 * D; i += 256) a_sh[i] = Ab[i];
    __syncthreads();

    float acc[16];
#pragma unroll
    for (int k = 0; k < 16; ++k) acc[k] = 0.f;

    for (int d0 = 0; d0 < D; d0 += 8) {
        float u[8];
#pragma unroll
        for (int i = 0; i < 8; ++i) u[i] = __ldg(Bm + (size_t)(d0 + i) * D + t);
#pragma unroll
        for (int k = 0; k < 16; ++k) {
            float4 h1 = *(const float4*)&a_sh[k * D + d0];
            float4 h2 = *(const float4*)&a_sh[k * D + d0 + 4];
            acc[k] = fmaf(h1.x, u[0], acc[k]); acc[k] = fmaf(h1.y, u[1], acc[k]);
            acc[k] = fmaf(h1.z, u[2], acc[k]); acc[k] = fmaf(h1.w, u[3], acc[k]);
            acc[k] = fmaf(h2.x, u[4], acc[k]); acc[k] = fmaf(h2.y, u[5], acc[k]);
            acc[k] = fmaf(h2.z, u[6], acc[k]); acc[k] = fmaf(h2.w, u[7], acc[k]);
        }
    }
#pragma unroll
    for (int k = 0; k < 16; ++k) Cb[k * D + t] = acc[k];
}

// encW tiles (0..511) + keysV tiles (512..767)
__global__ void gemm_pre_kernel(const float* __restrict__ keys,
                                const float* __restrict__ V,
                                const float* __restrict__ W) {
    int blk = blockIdx.x;
    if (blk < 512) {
        size_t off = (size_t)blk * 16 * D;
        gemm16_body(g_enc + off, W, g_encW + off);
    } else {
        size_t off = (size_t)(blk - 512) * 16 * D;
        gemm16_body(keys + off, V, g_keysV + off);
    }
}

// ---------------------------------------------------------------------------
// The scan. 256 CTAs = (batch, 16-row half). 256 threads, 2 CTAs/SM.
// GEMM: thread t = (dh = t>>7, cp = t&127): ALL 16 rows x cols (2cp, 2cp+1)
//       over d-half dh (64 packed pairs). Partials combined via padded smem.
// Epilogue: thread t = rows dh*8..dh*8+7 x cols (2cp, 2cp+1).
// Next-step gate dot + row norm fused into epilogue (h_new in hand).
// h kept UNNORMALIZED in smem; rs folded into gate/epilogue/output.
// ---------------------------------------------------------------------------
#define KH 16
#define PSTRIDE 65   // pacc row stride in floats (conflict-free)

__global__ void __launch_bounds__(256, 2)
scan_kernel(const int* __restrict__ pmask,
            float* __restrict__ out) {
    extern __shared__ float sm[];
    float* h       = sm;                      // KH*D       = 4096 floats
    float* kv_sh   = h + KH * D;              // KH*D       = 4096
    float* pacc    = kv_sh + KH * D;          // 128*PSTRIDE= 8320
    float* gate_sh = pacc + 128 * PSTRIDE;    // 16
    float* rs_sh   = gate_sh + KH;            // 16
    float* np_sh   = rs_sh + KH;              // 64
    float* gd_sh   = np_sh + KH * 4;          // 64
    int*   nxt     = (int*)(gd_sh + KH * 4);  // Sn + 1

    const int b    = blockIdx.x >> 1;
    const int half = blockIdx.x & 1;
    const int kgbl = half * KH;
    const int t    = threadIdx.x;
    const int cp   = t & 127;
    const int c0   = cp * 2;
    const int dh   = t >> 7;                 // d-half, also epilogue row group
    const int rb   = dh * 8;                 // epilogue rows rb..rb+7
    const int w    = t >> 5;
    const int wc   = w & 3;                  // col-group of this warp
    const int lane = t & 31;

    const size_t encRow = (size_t)b * Sn;

    if (t == 0) {
        int n = -1;
        for (int s = Sn - 1; s >= 0; --s) {
            nxt[s] = n;
            if (pmask[(encRow + s) * Ln] != 0) n = s;
        }
        nxt[Sn] = n;   // first active step
    }
    for (int i = t; i < KH * D; i += 256) {
        h[i] = 0.f;
        kv_sh[i] = g_keysV[((size_t)b * Kn + kgbl) * D + i];
    }
    if (t < KH) rs_sh[t] = 1.f;
    __syncthreads();

    int s = nxt[Sn];
    if (s >= 0 && t < KH) {  // first gate: h=0 -> sigmoid(eK)
        float ek = __ldg(g_eK + (encRow + s) * Kn + kgbl + t);
        gate_sh[t] = 1.f / (1.f + expf(-ek));
    }
    __syncthreads();

    const ulonglong2* Upk2 = (const ulonglong2*)g_Upk;  // [pair p][colpair cp]
    const int pbase = dh * 64;

    while (s >= 0) {
        const int snext = nxt[s];

        // ---- GEMM partial over d-half: 16 rows x 2 cols x 64 pairs ----
        unsigned long long accA[16], accB[16];
#pragma unroll
        for (int r = 0; r < 16; ++r) { accA[r] = 0ull; accB[r] = 0ull; }

        for (int g4 = 0; g4 < 64; g4 += 4) {
            const int p = pbase + g4;
            ulonglong2 u0 = __ldg(Upk2 + (size_t)(p + 0) * 128 + cp);
            ulonglong2 u1 = __ldg(Upk2 + (size_t)(p + 1) * 128 + cp);
            ulonglong2 u2 = __ldg(Upk2 + (size_t)(p + 2) * 128 + cp);
            ulonglong2 u3 = __ldg(Upk2 + (size_t)(p + 3) * 128 + cp);
#pragma unroll
            for (int r = 0; r < 16; ++r) {
                const ulonglong2* hp = (const ulonglong2*)&h[r * D + p * 2];
                ulonglong2 h01 = hp[0];
                ulonglong2 h23 = hp[1];
                FMA_F32X2(accA[r], h01.x, u0.x, accA[r]);
                FMA_F32X2(accB[r], h01.x, u0.y, accB[r]);
                FMA_F32X2(accA[r], h01.y, u1.x, accA[r]);
                FMA_F32X2(accB[r], h01.y, u1.y, accB[r]);
                FMA_F32X2(accA[r], h23.x, u2.x, accA[r]);
                FMA_F32X2(accB[r], h23.x, u2.y, accB[r]);
                FMA_F32X2(accA[r], h23.y, u3.x, accA[r]);
                FMA_F32X2(accB[r], h23.y, u3.y, accB[r]);
            }
        }
        // write partials: [cp][dh*32 + j], j=r for colA, 16+r for colB
        {
            float* pb = pacc + cp * PSTRIDE + dh * 32;
#pragma unroll
            for (int r = 0; r < 16; ++r) {
                float2 aA = *(float2*)&accA[r];
                float2 aB = *(float2*)&accB[r];
                pb[r]      = aA.x + aA.y;
                pb[16 + r] = aB.x + aB.y;
            }
        }
        __syncthreads();   // S1: partials ready; old-h reads done

        // ---- epilogue: rows rb..rb+7 x 2 cols ----
        const float2 ew = __ldg((const float2*)(g_encW + (encRow + s) * D + c0));
        float2 en = make_float2(0.f, 0.f);
        if (snext >= 0)
            en = __ldg((const float2*)(g_enc + (encRow + snext) * D + c0));

        float np[8], gd[8];
        const float* pb = pacc + cp * PSTRIDE;
#pragma unroll
        for (int j = 0; j < 8; ++j) {
            int   r  = rb + j;
            float huA = pb[r] + pb[32 + r];
            float huB = pb[16 + r] + pb[48 + r];
            float rs = rs_sh[r];
            float gt = gate_sh[r];
            float2 hold = *(float2*)&h[r * D + c0];
            float htA = fmaxf(fmaf(rs, huA, kv_sh[r * D + c0] + ew.x), 0.f);
            float htB = fmaxf(fmaf(rs, huB, kv_sh[r * D + c0 + 1] + ew.y), 0.f);
            float hA = fmaf(gt, htA, rs * hold.x);
            float hB = fmaf(gt, htB, rs * hold.y);
            *(float2*)&h[r * D + c0] = make_float2(hA, hB);
            np[j] = fmaf(hA, hA, hB * hB);
            gd[j] = fmaf(en.x, hA, en.y * hB);
        }
#pragma unroll
        for (int o = 16; o > 0; o >>= 1) {
#pragma unroll
            for (int j = 0; j < 8; ++j) {
                np[j] += __shfl_xor_sync(0xffffffffu, np[j], o);
                gd[j] += __shfl_xor_sync(0xffffffffu, gd[j], o);
            }
        }
        if (lane == 0) {
#pragma unroll
            for (int j = 0; j < 8; ++j) {
                np_sh[(rb + j) * 4 + wc] = np[j];
                gd_sh[(rb + j) * 4 + wc] = gd[j];
            }
        }
        __syncthreads();   // S2: partials + new h visible

        // ---- combine: rs + next gate (16 threads) ----
        if (t < KH) {
            float ssum = np_sh[t * 4 + 0] + np_sh[t * 4 + 1] +
                         np_sh[t * 4 + 2] + np_sh[t * 4 + 3];
            float rs = rsqrtf(fmaxf(ssum, 1e-12f));
            rs_sh[t] = rs;
            if (snext >= 0) {
                float gsum = gd_sh[t * 4 + 0] + gd_sh[t * 4 + 1] +
                             gd_sh[t * 4 + 2] + gd_sh[t * 4 + 3];
                float ek = __ldg(g_eK + (encRow + snext) * Kn + kgbl + t);
                gate_sh[t] = 1.f / (1.f + expf(-(fmaf(rs, gsum, ek))));
            }
        }
        s = snext;
        // rs/gate writes ordered vs next epilogue by next step's S1.
    }

    __syncthreads();   // final rs_sh / h visibility
    for (int i = t; i < KH * D; i += 256) {
        int r = i >> 8;
        out[((size_t)b * Kn + kgbl) * D + i] = h[i] * rs_sh[r];
    }
}

// ---------------------------------------------------------------------------
extern "C" void kernel_launch(void* const* d_in, const int* in_sizes, int n_in,
                              void* d_out, int out_size) {
    const int*   prgrph = (const int*)d_in[0];
    const int*   pmask  = (const int*)d_in[1];
    const float* keys   = (const float*)d_in[2];
    const float* emb    = (const float*)d_in[3];
    const float* U      = (const float*)d_in[4];
    const float* V      = (const float*)d_in[5];
    const float* W      = (const float*)d_in[6];
    float*       out    = (float*)d_out;

    const int scan_smem =
        (KH * D * 2 + 128 * PSTRIDE + KH * 10) * (int)sizeof(float) +
        (Sn + 1) * (int)sizeof(int) + 64;
    cudaFuncSetAttribute(scan_kernel, cudaFuncAttributeMaxDynamicSharedMemorySize,
                         scan_smem);

    gather_eK_kernel<<<Bn * Sn, 256>>>(prgrph, emb, keys);
    packU_kernel<<<D / 2, 256>>>(U);
    gemm_pre_kernel<<<768, 256>>>(keys, V, W);
    scan_kernel<<<Bn * 2, 256, scan_smem>>>(pmask, out);
}